// round 14
// baseline (speedup 1.0000x reference)
#include <cuda_runtime.h>
#include <math.h>

#define B   32
#define T   2048
#define H   1024
#define OUT 256

#define GRP    8                  // rows per group in main pass
#define NGRPS  (T / GRP)          // 256 groups per batch
#define NP     12                 // persistent CTAs per batch (12*32=384 = single wave)
#define HC     16                 // h-chunks for ht partial (64 each)
#define PREP_CTAS 512             // prep kernel grid (co-resident at 4/SM)

// ---- scratch (__device__ globals; no allocation allowed) ----
__device__ float d_htp[HC * B * H];                   // h_t partials
__device__ float d_ht [B * H];                        // h_t
__device__ float d_v  [B * H];                        // v[b] = W1 @ h_t[b]
__device__ float d_scr[(size_t)B * NP * H];           // per-CTA context partials (1.5MB)
__device__ float d_md [B * NP * 2];                   // per-CTA (m, d)
__device__ int           p_cnt;                       // prep barrier arrivals (zero-init)
__device__ volatile int  p_gen;                       // prep barrier generation (monotonic)
__device__ int           b_cnt[B];                    // per-batch arrivals (zero-init)
__device__ volatile int  b_gen[B];                    // per-batch generation (monotonic)

// software grid barrier for prep (512 co-resident CTAs)
__device__ __forceinline__ void prep_sync() {
    __threadfence();
    __syncthreads();
    if (threadIdx.x == 0) {
        int gen = p_gen;
        if (atomicAdd(&p_cnt, 1) == PREP_CTAS - 1) {
            p_cnt = 0;
            __threadfence();
            p_gen = gen + 1;
        } else {
            while (p_gen == gen) __nanosleep(64);
            __threadfence();
        }
    }
    __syncthreads();
}

// ================= prep: h_t partials -> reduce -> v, one kernel
// grid 512 CTAs, 256 threads, guaranteed co-resident (4 CTAs/SM).
__global__ void __launch_bounds__(256, 4) prep_kernel(const float* __restrict__ hs,
                                                      const float* __restrict__ W1,
                                                      const float* __restrict__ b1) {
    const int c   = blockIdx.x;
    const int tid = threadIdx.x;
    const int w   = tid >> 5, lane = tid & 31;

    __shared__ __align__(16) char sm_raw[16384];
    float (*hsl)[64] = (float (*)[64])sm_raw;   // phase A: 32x64 = 8KB
    float (*hts)[H]  = (float (*)[H])sm_raw;    // phase B: 4x1024 = 16KB

    // ---- Phase A: h_t partials. c -> (kt = c&31, hc = c>>5) ----
    {
        int kt = c & 31, hc = c >> 5;
        int h0 = hc * 64;
        for (int i = tid; i < B * 64; i += 256) {
            int b = i >> 6, hh = i & 63;
            hsl[b][hh] = hs[((size_t)b * T + (T - 1)) * H + h0 + hh];
        }
        __syncthreads();
        int k = kt * 32 + lane;
        int b0 = w * 4;
        float a0 = 0.f, a1 = 0.f, a2 = 0.f, a3 = 0.f;
        const float* w1p = W1 + (size_t)h0 * H + k;
#pragma unroll 16
        for (int hh = 0; hh < 64; hh++) {
            float wv = w1p[(size_t)hh * H];
            a0 = fmaf(hsl[b0 + 0][hh], wv, a0);
            a1 = fmaf(hsl[b0 + 1][hh], wv, a1);
            a2 = fmaf(hsl[b0 + 2][hh], wv, a2);
            a3 = fmaf(hsl[b0 + 3][hh], wv, a3);
        }
        d_htp[((size_t)hc * B + b0 + 0) * H + k] = a0;
        d_htp[((size_t)hc * B + b0 + 1) * H + k] = a1;
        d_htp[((size_t)hc * B + b0 + 2) * H + k] = a2;
        d_htp[((size_t)hc * B + b0 + 3) * H + k] = a3;
    }
    prep_sync();

    // ---- Phase A2: h_t reduce + bias (first 128 CTAs) ----
    if (c < 128) {
        int g = c * 256 + tid;              // 0..32767
        int bb = g >> 10, k = g & (H - 1);
        float a = b1[k];
#pragma unroll
        for (int hc = 0; hc < HC; hc++) a += d_htp[((size_t)hc * B + bb) * H + k];
        d_ht[(size_t)bb * H + k] = a;
    }
    prep_sync();

    // ---- Phase B: v[b,h] = W1[h,:] . h_t[b,:]. c -> (bg = c&7, base = c>>3) ----
    {
        int bg = c & 7, base = c >> 3;      // base 0..63
        for (int i = tid; i < 4 * H; i += 256) {
            int bi = i >> 10, k = i & (H - 1);
            hts[bi][k] = d_ht[(size_t)(bg * 4 + bi) * H + k];
        }
        __syncthreads();
#pragma unroll
        for (int rep = 0; rep < 2; rep++) {
            int ht8 = base + rep * 64;      // 2 h-tiles per CTA
            int h = ht8 * 8 + w;
            const float4* row = (const float4*)(W1 + (size_t)h * H);
            float a0 = 0.f, a1 = 0.f, a2 = 0.f, a3 = 0.f;
#pragma unroll
            for (int ki = 0; ki < 8; ki++) {
                float4 wv = row[ki * 32 + lane];
                int kb = (ki * 32 + lane) * 4;
                float4 t0 = *(const float4*)&hts[0][kb];
                float4 t1 = *(const float4*)&hts[1][kb];
                float4 t2 = *(const float4*)&hts[2][kb];
                float4 t3 = *(const float4*)&hts[3][kb];
                a0 = fmaf(wv.x, t0.x, fmaf(wv.y, t0.y, fmaf(wv.z, t0.z, fmaf(wv.w, t0.w, a0))));
                a1 = fmaf(wv.x, t1.x, fmaf(wv.y, t1.y, fmaf(wv.z, t1.z, fmaf(wv.w, t1.w, a1))));
                a2 = fmaf(wv.x, t2.x, fmaf(wv.y, t2.y, fmaf(wv.z, t2.z, fmaf(wv.w, t2.w, a2))));
                a3 = fmaf(wv.x, t3.x, fmaf(wv.y, t3.y, fmaf(wv.z, t3.z, fmaf(wv.w, t3.w, a3))));
            }
#pragma unroll
            for (int off = 16; off; off >>= 1) {
                a0 += __shfl_xor_sync(0xffffffffu, a0, off);
                a1 += __shfl_xor_sync(0xffffffffu, a1, off);
                a2 += __shfl_xor_sync(0xffffffffu, a2, off);
                a3 += __shfl_xor_sync(0xffffffffu, a3, off);
            }
            if (lane == 0) {
                d_v[(size_t)(bg * 4 + 0) * H + h] = a0;
                d_v[(size_t)(bg * 4 + 1) * H + h] = a1;
                d_v[(size_t)(bg * 4 + 2) * H + h] = a2;
                d_v[(size_t)(bg * 4 + 3) * H + h] = a3;
            }
        }
    }
}

// ================= main: streaming softmax pass + absorbed tail
// grid (NP, B) = 384 CTAs, single wave at 3 CTAs/SM (proven co-resident).
__global__ void __launch_bounds__(256, 3) main_pass_kernel(const float* __restrict__ hs,
                                                           const float* __restrict__ Wv,
                                                           const float* __restrict__ bv,
                                                           float* __restrict__ out) {
    const int p   = blockIdx.x;
    const int b   = blockIdx.y;
    const int tid = threadIdx.x;
    const int w   = tid >> 5, lane = tid & 31;

    __shared__ float part[2][GRP][8];
    __shared__ float pre[2 * H];
    __shared__ float red[8][32];
    __shared__ float wcs[NP];
    __shared__ float invDs;

    // ---- streaming phase (unchanged, proven ~42us body) ----
    {
        float4 vr = ((const float4*)(d_v + (size_t)b * H))[tid];
        float4 sa = make_float4(0.f, 0.f, 0.f, 0.f);
        float m = -INFINITY, d = 0.f;

        int g0 = (p * NGRPS) / NP;
        int g1 = ((p + 1) * NGRPS) / NP;
        const float4* base = (const float4*)(hs + (size_t)b * T * H) + tid;

        for (int g = g0; g < g1; g++) {
            float4 val[GRP];
#pragma unroll
            for (int j = 0; j < GRP; j++)
                val[j] = __ldcs(base + (size_t)(g * GRP + j) * (H / 4));

            float pd[GRP];
#pragma unroll
            for (int j = 0; j < GRP; j++)
                pd[j] = fmaf(val[j].x, vr.x, fmaf(val[j].y, vr.y,
                        fmaf(val[j].z, vr.z, val[j].w * vr.w)));
#pragma unroll
            for (int off = 16; off; off >>= 1) {
#pragma unroll
                for (int j = 0; j < GRP; j++)
                    pd[j] += __shfl_xor_sync(0xffffffffu, pd[j], off);
            }
            if (lane == 0) {
#pragma unroll
                for (int j = 0; j < GRP; j++) part[g & 1][j][w] = pd[j];
            }
            __syncthreads();

            float dt[GRP];
#pragma unroll
            for (int j = 0; j < GRP; j++) {
                float4 x = *(const float4*)&part[g & 1][j][0];
                float4 y = *(const float4*)&part[g & 1][j][4];
                dt[j] = ((x.x + x.y) + (x.z + x.w)) + ((y.x + y.y) + (y.z + y.w));
            }
#pragma unroll
            for (int j = 0; j < GRP; j++) {
                float mn = fmaxf(m, dt[j]);
                float sc = __expf(m - mn);      // 0 on first row (m=-inf)
                float wt = __expf(dt[j] - mn);
                d = d * sc + wt;
                sa.x = fmaf(sa.x, sc, wt * val[j].x);
                sa.y = fmaf(sa.y, sc, wt * val[j].y);
                sa.z = fmaf(sa.z, sc, wt * val[j].z);
                sa.w = fmaf(sa.w, sc, wt * val[j].w);
                m = mn;
            }
        }
        ((float4*)(d_scr + (size_t)(b * NP + p) * H))[tid] = sa;
        if (tid == 0) {
            d_md[(b * NP + p) * 2 + 0] = m;
            d_md[(b * NP + p) * 2 + 1] = d;
        }
    }

    // ---- per-batch barrier: wait for all 12 CTAs of this b ----
    __threadfence();
    __syncthreads();
    if (tid == 0) {
        int gen = b_gen[b];
        if (atomicAdd(&b_cnt[b], 1) == NP - 1) {
            b_cnt[b] = 0;
            __threadfence();
            b_gen[b] = gen + 1;
        } else {
            while (b_gen[b] == gen) __nanosleep(32);
            __threadfence();
        }
    }
    __syncthreads();

    // ---- absorbed tail: CTAs p<8 do combine + Wv GEMM + tanh for batch b ----
    if (p < 8) {
        int ot = p;
        if (tid == 0) {
            float mloc[NP], dloc[NP];
#pragma unroll
            for (int c = 0; c < NP; c++) {
                mloc[c] = d_md[(b * NP + c) * 2 + 0];
                dloc[c] = d_md[(b * NP + c) * 2 + 1];
            }
            float M = mloc[0];
#pragma unroll
            for (int c = 1; c < NP; c++) M = fmaxf(M, mloc[c]);
            float D = 0.f;
#pragma unroll
            for (int c = 0; c < NP; c++) {
                float wv = __expf(mloc[c] - M);
                wcs[c] = wv;
                D += wv * dloc[c];
            }
            invDs = 1.f / D;
        }
        __syncthreads();
        float invD = invDs;

#pragma unroll
        for (int q = 0; q < 4; q++) {
            int h = q * 256 + tid;
            float a = 0.f;
#pragma unroll
            for (int c = 0; c < NP; c++)
                a = fmaf(wcs[c], d_scr[(size_t)(b * NP + c) * H + h], a);
            pre[h]     = a * invD;
            pre[H + h] = d_ht[(size_t)b * H + h];
        }
        __syncthreads();

        int o   = ot * 32 + lane;
        int seg = w;                         // 8 segments x 256 j
        const float* wp = Wv + (size_t)(seg * 256) * OUT + o;
        const float* pp = pre + seg * 256;
        float acc = 0.f;
        for (int base = 0; base < 256; base += 8) {
            float wb[8];
#pragma unroll
            for (int i = 0; i < 8; i++) wb[i] = wp[(size_t)(base + i) * OUT];
#pragma unroll
            for (int i = 0; i < 8; i++) acc = fmaf(pp[base + i], wb[i], acc);
        }
        red[w][lane] = acc;
        __syncthreads();

        if (tid < 32) {
            float a = bv[ot * 32 + tid];
#pragma unroll
            for (int k = 0; k < 8; k++) a += red[k][tid];
            out[(size_t)b * OUT + ot * 32 + tid] = tanhf(a);
        }
    }
}

extern "C" void kernel_launch(void* const* d_in, const int* in_sizes, int n_in,
                              void* d_out, int out_size) {
    const float* hs = (const float*)d_in[0];
    const float* W1 = (const float*)d_in[1];
    const float* b1 = (const float*)d_in[2];
    const float* Wv = (const float*)d_in[3];
    const float* bv = (const float*)d_in[4];
    float* out = (float*)d_out;

    prep_kernel<<<PREP_CTAS, 256>>>(hs, W1, b1);
    main_pass_kernel<<<dim3(NP, B), 256>>>(hs, Wv, bv, out);
}

// round 16
// speedup vs baseline: 1.0278x; 1.0278x over previous
#include <cuda_runtime.h>
#include <math.h>

#define B   32
#define T   2048
#define H   1024
#define OUT 256

#define GRP    4                  // rows per group in main pass
#define NGRPS  (T / GRP)          // 512 groups per batch
#define NP     12                 // persistent CTAs per batch (12*32=384 = single wave)
#define HC     16                 // h-chunks for ht partial (64 each)

// ---- scratch (__device__ globals; no allocation allowed) ----
__device__ float d_htp[HC * B * H];                   // h_t partials
__device__ float d_ht [B * H];                        // h_t
__device__ float d_v  [B * H];                        // v[b] = W1 @ h_t[b]
__device__ float d_scr[(size_t)B * NP * H];           // per-CTA context partials (1.5MB)
__device__ float d_md [B * NP * 2];                   // per-CTA (m, d)
__device__ int   d_cnt[32];                           // per-kt arrival counters (zero-init)

// ================= h_t: partial + last-block reduce (fused via counter)
__global__ void __launch_bounds__(256) ht_kernel(const float* __restrict__ hs,
                                                 const float* __restrict__ W1,
                                                 const float* __restrict__ b1) {
    int kt = blockIdx.x, hc = blockIdx.y;
    int tid = threadIdx.x;
    int kl = tid & 31, bg = tid >> 5;
    __shared__ float hsl[B][64];
    int h0 = hc * 64;
    for (int i = tid; i < B * 64; i += 256) {
        int b = i >> 6, hh = i & 63;
        hsl[b][hh] = hs[((size_t)b * T + (T - 1)) * H + h0 + hh];
    }
    __syncthreads();
    int k = kt * 32 + kl;
    int b0 = bg * 4;
    float a0 = 0.f, a1 = 0.f, a2 = 0.f, a3 = 0.f;
    const float* w1p = W1 + (size_t)h0 * H + k;
#pragma unroll 16
    for (int hh = 0; hh < 64; hh++) {
        float w = w1p[(size_t)hh * H];
        a0 = fmaf(hsl[b0 + 0][hh], w, a0);
        a1 = fmaf(hsl[b0 + 1][hh], w, a1);
        a2 = fmaf(hsl[b0 + 2][hh], w, a2);
        a3 = fmaf(hsl[b0 + 3][hh], w, a3);
    }
    d_htp[((size_t)hc * B + b0 + 0) * H + k] = a0;
    d_htp[((size_t)hc * B + b0 + 1) * H + k] = a1;
    d_htp[((size_t)hc * B + b0 + 2) * H + k] = a2;
    d_htp[((size_t)hc * B + b0 + 3) * H + k] = a3;

    __threadfence();
    __syncthreads();
    __shared__ int amLast;
    if (tid == 0) amLast = (atomicAdd(&d_cnt[kt], 1) == HC - 1);
    __syncthreads();
    if (amLast) {
#pragma unroll
        for (int i = 0; i < 4; i++) {
            int b = (tid >> 5) * 4 + i;
            float a = b1[k];
#pragma unroll
            for (int c = 0; c < HC; c++) a += d_htp[((size_t)c * B + b) * H + k];
            d_ht[(size_t)b * H + k] = a;
        }
        if (tid == 0) d_cnt[kt] = 0;   // reset for next graph replay
    }
}

// ================= v[b,h] = dot(W1 row h, h_t[b])
__global__ void __launch_bounds__(256) v_kernel(const float* __restrict__ W1) {
    int ht8 = blockIdx.x, bg = blockIdx.y;
    int tid = threadIdx.x;
    int w = tid >> 5, lane = tid & 31;
    __shared__ float hts[4][H];
    for (int i = tid; i < 4 * H; i += 256) {
        int bi = i >> 10, k = i & (H - 1);
        hts[bi][k] = d_ht[(size_t)(bg * 4 + bi) * H + k];
    }
    __syncthreads();
    int h = ht8 * 8 + w;
    const float4* row = (const float4*)(W1 + (size_t)h * H);
    float a0 = 0.f, a1 = 0.f, a2 = 0.f, a3 = 0.f;
#pragma unroll
    for (int ki = 0; ki < 8; ki++) {
        float4 wv = row[ki * 32 + lane];
        int kb = (ki * 32 + lane) * 4;
        float4 t0 = *(const float4*)&hts[0][kb];
        float4 t1 = *(const float4*)&hts[1][kb];
        float4 t2 = *(const float4*)&hts[2][kb];
        float4 t3 = *(const float4*)&hts[3][kb];
        a0 = fmaf(wv.x, t0.x, fmaf(wv.y, t0.y, fmaf(wv.z, t0.z, fmaf(wv.w, t0.w, a0))));
        a1 = fmaf(wv.x, t1.x, fmaf(wv.y, t1.y, fmaf(wv.z, t1.z, fmaf(wv.w, t1.w, a1))));
        a2 = fmaf(wv.x, t2.x, fmaf(wv.y, t2.y, fmaf(wv.z, t2.z, fmaf(wv.w, t2.w, a2))));
        a3 = fmaf(wv.x, t3.x, fmaf(wv.y, t3.y, fmaf(wv.z, t3.z, fmaf(wv.w, t3.w, a3))));
    }
#pragma unroll
    for (int off = 16; off; off >>= 1) {
        a0 += __shfl_xor_sync(0xffffffffu, a0, off);
        a1 += __shfl_xor_sync(0xffffffffu, a1, off);
        a2 += __shfl_xor_sync(0xffffffffu, a2, off);
        a3 += __shfl_xor_sync(0xffffffffu, a3, off);
    }
    if (lane == 0) {
        d_v[(size_t)(bg * 4 + 0) * H + h] = a0;
        d_v[(size_t)(bg * 4 + 1) * H + h] = a1;
        d_v[(size_t)(bg * 4 + 2) * H + h] = a2;
        d_v[(size_t)(bg * 4 + 3) * H + h] = a3;
    }
}

// ================= main streaming pass: cross-group double-buffered loads
// grid (NP, B), 256 threads. GRP=4: next group's loads issue BEFORE the
// current group's reduce/update, keeping DRAM fed through the bubble.
__global__ void __launch_bounds__(256) main_pass_kernel(const float* __restrict__ hs) {
    int p = blockIdx.x;
    int b = blockIdx.y;
    int tid = threadIdx.x;
    int w = tid >> 5, lane = tid & 31;

    __shared__ float part[2][GRP][8];

    float4 vr = ((const float4*)(d_v + (size_t)b * H))[tid];
    float4 sa = make_float4(0.f, 0.f, 0.f, 0.f);
    float m = -INFINITY, d = 0.f;

    int g0 = (p * NGRPS) / NP;
    int g1 = ((p + 1) * NGRPS) / NP;

    const float4* base = (const float4*)(hs + (size_t)b * T * H) + tid;

    float4 val[GRP];
#pragma unroll
    for (int j = 0; j < GRP; j++)
        val[j] = __ldcs(base + (size_t)(g0 * GRP + j) * (H / 4));

    for (int g = g0; g < g1; g++) {
        int gn = (g + 1 < g1) ? g + 1 : g;
        float4 valn[GRP];
#pragma unroll
        for (int j = 0; j < GRP; j++)
            valn[j] = __ldcs(base + (size_t)(gn * GRP + j) * (H / 4));

        float pd[GRP];
#pragma unroll
        for (int j = 0; j < GRP; j++)
            pd[j] = fmaf(val[j].x, vr.x, fmaf(val[j].y, vr.y,
                    fmaf(val[j].z, vr.z, val[j].w * vr.w)));
#pragma unroll
        for (int off = 16; off; off >>= 1) {
#pragma unroll
            for (int j = 0; j < GRP; j++)
                pd[j] += __shfl_xor_sync(0xffffffffu, pd[j], off);
        }
        if (lane == 0) {
#pragma unroll
            for (int j = 0; j < GRP; j++) part[g & 1][j][w] = pd[j];
        }
        __syncthreads();

        float dt[GRP];
#pragma unroll
        for (int j = 0; j < GRP; j++) {
            float4 x = *(const float4*)&part[g & 1][j][0];
            float4 y = *(const float4*)&part[g & 1][j][4];
            dt[j] = ((x.x + x.y) + (x.z + x.w)) + ((y.x + y.y) + (y.z + y.w));
        }
#pragma unroll
        for (int j = 0; j < GRP; j++) {
            float mn = fmaxf(m, dt[j]);
            float sc = __expf(m - mn);      // 0 on first row (m=-inf)
            float wt = __expf(dt[j] - mn);
            d = d * sc + wt;
            sa.x = fmaf(sa.x, sc, wt * val[j].x);
            sa.y = fmaf(sa.y, sc, wt * val[j].y);
            sa.z = fmaf(sa.z, sc, wt * val[j].z);
            sa.w = fmaf(sa.w, sc, wt * val[j].w);
            m = mn;
        }
#pragma unroll
        for (int j = 0; j < GRP; j++) val[j] = valn[j];
    }

    ((float4*)(d_scr + (size_t)(b * NP + p) * H))[tid] = sa;
    if (tid == 0) {
        d_md[(b * NP + p) * 2 + 0] = m;
        d_md[(b * NP + p) * 2 + 1] = d;
    }
}

// ================= tail: combine + Wv GEMM + tanh (smem-staged, prefetched)
// grid (B, 8 o-tiles of 32), 512 threads.
// wsm pitch = 36 floats = 144B (16B-aligned -> legal STS.128; reads are
// lane-consecutive wsm[j][lane] -> conflict-free regardless of pitch).
__global__ void __launch_bounds__(512) tail_kernel(const float* __restrict__ Wv,
                                                   const float* __restrict__ bv,
                                                   float* __restrict__ out) {
    int b = blockIdx.x, ot = blockIdx.y;
    int tid = threadIdx.x;
    int w = tid >> 5, lane = tid & 31;    // 16 warps, lane = o within tile

    __shared__ float pre[2 * H];                       // 8KB
    __shared__ __align__(16) float wsm[256][36];       // 36KB Wv tile [j][o], 16B-aligned pitch
    __shared__ float red[16][32];
    __shared__ float wcs[NP];
    __shared__ float invDs;

    if (tid == 0) {
        float mloc[NP], dloc[NP];
#pragma unroll
        for (int c = 0; c < NP; c++) {
            mloc[c] = d_md[(b * NP + c) * 2 + 0];
            dloc[c] = d_md[(b * NP + c) * 2 + 1];
        }
        float M = mloc[0];
#pragma unroll
        for (int c = 1; c < NP; c++) M = fmaxf(M, mloc[c]);
        float D = 0.f;
#pragma unroll
        for (int c = 0; c < NP; c++) {
            float wv = __expf(mloc[c] - M);
            wcs[c] = wv;
            D += wv * dloc[c];
        }
        invDs = 1.f / D;
    }
    __syncthreads();
    float invD = invDs;

#pragma unroll
    for (int q = 0; q < 2; q++) {
        int h = q * 512 + tid;
        float a = 0.f;
#pragma unroll
        for (int c = 0; c < NP; c++)
            a = fmaf(wcs[c], d_scr[(size_t)(b * NP + c) * H + h], a);
        pre[h]     = a * invD;
        pre[H + h] = d_ht[(size_t)b * H + h];
    }

    // GEMM: 8 j-tiles of 256. Loader: row = tid>>1, half = tid&1 (16 floats).
    int row = tid >> 1, half = tid & 1;
    const float* wbase = Wv + (size_t)row * OUT + ot * 32 + half * 16;

    float4 pf[4];
#pragma unroll
    for (int i = 0; i < 4; i++)
        pf[i] = *(const float4*)(wbase + i * 4);    // tile 0 prefetch

    float acc = 0.f;
    for (int jt = 0; jt < 8; jt++) {
#pragma unroll
        for (int i = 0; i < 4; i++)
            *(float4*)&wsm[row][half * 16 + i * 4] = pf[i];
        __syncthreads();

        if (jt < 7) {
            const float* src = wbase + (size_t)(jt + 1) * 256 * OUT;
#pragma unroll
            for (int i = 0; i < 4; i++)
                pf[i] = *(const float4*)(src + i * 4);   // overlap with compute
        }

        const float* pj = pre + jt * 256 + w * 16;
#pragma unroll
        for (int i = 0; i < 16; i++)
            acc = fmaf(pj[i], wsm[w * 16 + i][lane], acc);
        __syncthreads();
    }

    red[w][lane] = acc;
    __syncthreads();
    if (tid < 32) {
        float a = bv[ot * 32 + tid];
#pragma unroll
        for (int k = 0; k < 16; k++) a += red[k][tid];
        out[(size_t)b * OUT + ot * 32 + tid] = tanhf(a);
    }
}

extern "C" void kernel_launch(void* const* d_in, const int* in_sizes, int n_in,
                              void* d_out, int out_size) {
    const float* hs = (const float*)d_in[0];
    const float* W1 = (const float*)d_in[1];
    const float* b1 = (const float*)d_in[2];
    const float* Wv = (const float*)d_in[3];
    const float* bv = (const float*)d_in[4];
    float* out = (float*)d_out;

    ht_kernel<<<dim3(32, HC), 256>>>(hs, W1, b1);
    v_kernel<<<dim3(128, 8), 256>>>(W1);
    main_pass_kernel<<<dim3(NP, B), 256>>>(hs);
    tail_kernel<<<dim3(B, 8), 512>>>(Wv, bv, out);
}

// round 17
// speedup vs baseline: 1.1553x; 1.1241x over previous
#include <cuda_runtime.h>
#include <math.h>

#define B   32
#define T   2048
#define H   1024
#define OUT 256

#define GRP    8                  // rows per group in main pass
#define NGRPS  (T / GRP)          // 256 groups per batch
#define NP     12                 // persistent CTAs per batch (12*32=384 = single wave)
#define HC     16                 // h-chunks for ht partial (64 each)

// ---- scratch (__device__ globals; no allocation allowed) ----
__device__ float d_htp[HC * B * H];                   // h_t partials
__device__ float d_ht [B * H];                        // h_t
__device__ float d_v  [B * H];                        // v[b] = W1 @ h_t[b]
__device__ float d_scr[(size_t)B * NP * H];           // per-CTA context partials (1.5MB)
__device__ float d_md [B * NP * 2];                   // per-CTA (m, d)
__device__ int   d_cnt[32];                           // per-kt arrival counters (zero-init)

// ================= h_t: partial + last-block reduce (fused via counter)
__global__ void __launch_bounds__(256) ht_kernel(const float* __restrict__ hs,
                                                 const float* __restrict__ W1,
                                                 const float* __restrict__ b1) {
    int kt = blockIdx.x, hc = blockIdx.y;
    int tid = threadIdx.x;
    int kl = tid & 31, bg = tid >> 5;
    __shared__ float hsl[B][64];
    int h0 = hc * 64;
    for (int i = tid; i < B * 64; i += 256) {
        int b = i >> 6, hh = i & 63;
        hsl[b][hh] = hs[((size_t)b * T + (T - 1)) * H + h0 + hh];
    }
    __syncthreads();
    int k = kt * 32 + kl;
    int b0 = bg * 4;
    float a0 = 0.f, a1 = 0.f, a2 = 0.f, a3 = 0.f;
    const float* w1p = W1 + (size_t)h0 * H + k;
#pragma unroll 16
    for (int hh = 0; hh < 64; hh++) {
        float w = w1p[(size_t)hh * H];
        a0 = fmaf(hsl[b0 + 0][hh], w, a0);
        a1 = fmaf(hsl[b0 + 1][hh], w, a1);
        a2 = fmaf(hsl[b0 + 2][hh], w, a2);
        a3 = fmaf(hsl[b0 + 3][hh], w, a3);
    }
    d_htp[((size_t)hc * B + b0 + 0) * H + k] = a0;
    d_htp[((size_t)hc * B + b0 + 1) * H + k] = a1;
    d_htp[((size_t)hc * B + b0 + 2) * H + k] = a2;
    d_htp[((size_t)hc * B + b0 + 3) * H + k] = a3;

    __threadfence();
    __syncthreads();
    __shared__ int amLast;
    if (tid == 0) amLast = (atomicAdd(&d_cnt[kt], 1) == HC - 1);
    __syncthreads();
    if (amLast) {
#pragma unroll
        for (int i = 0; i < 4; i++) {
            int b = (tid >> 5) * 4 + i;
            float a = b1[k];
#pragma unroll
            for (int c = 0; c < HC; c++) a += d_htp[((size_t)c * B + b) * H + k];
            d_ht[(size_t)b * H + k] = a;
        }
        if (tid == 0) d_cnt[kt] = 0;   // reset for next graph replay
    }
}

// ================= v[b,h] = dot(W1 row h, h_t[b])
__global__ void __launch_bounds__(256) v_kernel(const float* __restrict__ W1) {
    int ht8 = blockIdx.x, bg = blockIdx.y;
    int tid = threadIdx.x;
    int w = tid >> 5, lane = tid & 31;
    __shared__ float hts[4][H];
    for (int i = tid; i < 4 * H; i += 256) {
        int bi = i >> 10, k = i & (H - 1);
        hts[bi][k] = d_ht[(size_t)(bg * 4 + bi) * H + k];
    }
    __syncthreads();
    int h = ht8 * 8 + w;
    const float4* row = (const float4*)(W1 + (size_t)h * H);
    float a0 = 0.f, a1 = 0.f, a2 = 0.f, a3 = 0.f;
#pragma unroll
    for (int ki = 0; ki < 8; ki++) {
        float4 wv = row[ki * 32 + lane];
        int kb = (ki * 32 + lane) * 4;
        float4 t0 = *(const float4*)&hts[0][kb];
        float4 t1 = *(const float4*)&hts[1][kb];
        float4 t2 = *(const float4*)&hts[2][kb];
        float4 t3 = *(const float4*)&hts[3][kb];
        a0 = fmaf(wv.x, t0.x, fmaf(wv.y, t0.y, fmaf(wv.z, t0.z, fmaf(wv.w, t0.w, a0))));
        a1 = fmaf(wv.x, t1.x, fmaf(wv.y, t1.y, fmaf(wv.z, t1.z, fmaf(wv.w, t1.w, a1))));
        a2 = fmaf(wv.x, t2.x, fmaf(wv.y, t2.y, fmaf(wv.z, t2.z, fmaf(wv.w, t2.w, a2))));
        a3 = fmaf(wv.x, t3.x, fmaf(wv.y, t3.y, fmaf(wv.z, t3.z, fmaf(wv.w, t3.w, a3))));
    }
#pragma unroll
    for (int off = 16; off; off >>= 1) {
        a0 += __shfl_xor_sync(0xffffffffu, a0, off);
        a1 += __shfl_xor_sync(0xffffffffu, a1, off);
        a2 += __shfl_xor_sync(0xffffffffu, a2, off);
        a3 += __shfl_xor_sync(0xffffffffu, a3, off);
    }
    if (lane == 0) {
        d_v[(size_t)(bg * 4 + 0) * H + h] = a0;
        d_v[(size_t)(bg * 4 + 1) * H + h] = a1;
        d_v[(size_t)(bg * 4 + 2) * H + h] = a2;
        d_v[(size_t)(bg * 4 + 3) * H + h] = a3;
    }
}

// ================= main streaming pass: persistent single wave (R13 proven)
__global__ void __launch_bounds__(256) main_pass_kernel(const float* __restrict__ hs) {
    int p = blockIdx.x;
    int b = blockIdx.y;
    int tid = threadIdx.x;
    int w = tid >> 5, lane = tid & 31;

    __shared__ float part[2][GRP][8];

    float4 vr = ((const float4*)(d_v + (size_t)b * H))[tid];
    float4 sa = make_float4(0.f, 0.f, 0.f, 0.f);
    float m = -INFINITY, d = 0.f;

    int g0 = (p * NGRPS) / NP;
    int g1 = ((p + 1) * NGRPS) / NP;

    const float4* base = (const float4*)(hs + (size_t)b * T * H) + tid;

    for (int g = g0; g < g1; g++) {
        float4 val[GRP];
#pragma unroll
        for (int j = 0; j < GRP; j++)
            val[j] = __ldcs(base + (size_t)(g * GRP + j) * (H / 4));

        float pd[GRP];
#pragma unroll
        for (int j = 0; j < GRP; j++)
            pd[j] = fmaf(val[j].x, vr.x, fmaf(val[j].y, vr.y,
                    fmaf(val[j].z, vr.z, val[j].w * vr.w)));

#pragma unroll
        for (int off = 16; off; off >>= 1) {
#pragma unroll
            for (int j = 0; j < GRP; j++)
                pd[j] += __shfl_xor_sync(0xffffffffu, pd[j], off);
        }
        if (lane == 0) {
#pragma unroll
            for (int j = 0; j < GRP; j++) part[g & 1][j][w] = pd[j];
        }
        __syncthreads();

        float dt[GRP];
#pragma unroll
        for (int j = 0; j < GRP; j++) {
            float4 x = *(const float4*)&part[g & 1][j][0];
            float4 y = *(const float4*)&part[g & 1][j][4];
            dt[j] = ((x.x + x.y) + (x.z + x.w)) + ((y.x + y.y) + (y.z + y.w));
        }
#pragma unroll
        for (int j = 0; j < GRP; j++) {
            float mn = fmaxf(m, dt[j]);
            float sc = __expf(m - mn);      // 0 on first row (m=-inf)
            float wt = __expf(dt[j] - mn);
            d = d * sc + wt;
            sa.x = fmaf(sa.x, sc, wt * val[j].x);
            sa.y = fmaf(sa.y, sc, wt * val[j].y);
            sa.z = fmaf(sa.z, sc, wt * val[j].z);
            sa.w = fmaf(sa.w, sc, wt * val[j].w);
            m = mn;
        }
    }

    ((float4*)(d_scr + (size_t)(b * NP + p) * H))[tid] = sa;
    if (tid == 0) {
        d_md[(b * NP + p) * 2 + 0] = m;
        d_md[(b * NP + p) * 2 + 1] = d;
    }
}

// ================= tail: combine + Wv GEMM + tanh (16-wide register batches)
// grid (B, 8 o-tiles of 32), 512 threads.
// thread = (o = tid&31, seg = tid>>5 of 16 segments x 128 j).
__global__ void __launch_bounds__(512) tail_kernel(const float* __restrict__ Wv,
                                                   const float* __restrict__ bv,
                                                   float* __restrict__ out) {
    int b = blockIdx.x, ot = blockIdx.y;
    int tid = threadIdx.x;

    __shared__ float pre[2 * H];
    __shared__ float wcs[NP];
    __shared__ float invDs;
    __shared__ float red[16][32];

    if (tid == 0) {
        float mloc[NP], dloc[NP];
#pragma unroll
        for (int c = 0; c < NP; c++) {
            mloc[c] = d_md[(b * NP + c) * 2 + 0];
            dloc[c] = d_md[(b * NP + c) * 2 + 1];
        }
        float M = mloc[0];
#pragma unroll
        for (int c = 1; c < NP; c++) M = fmaxf(M, mloc[c]);
        float D = 0.f;
#pragma unroll
        for (int c = 0; c < NP; c++) {
            float wv = __expf(mloc[c] - M);
            wcs[c] = wv;
            D += wv * dloc[c];
        }
        invDs = 1.f / D;
    }
    __syncthreads();
    float invD = invDs;

#pragma unroll
    for (int q = 0; q < 2; q++) {
        int h = q * 512 + tid;
        float a = 0.f;
#pragma unroll
        for (int c = 0; c < NP; c++)
            a = fmaf(wcs[c], d_scr[(size_t)(b * NP + c) * H + h], a);
        pre[h]     = a * invD;
        pre[H + h] = d_ht[(size_t)b * H + h];
    }
    __syncthreads();

    int o   = ot * 32 + (tid & 31);
    int seg = tid >> 5;                      // 0..15
    const float* wp = Wv + (size_t)(seg * 128) * OUT + o;
    const float* pp = pre + seg * 128;
    float acc = 0.f;
#pragma unroll
    for (int base = 0; base < 128; base += 16) {
        float wb[16];
#pragma unroll
        for (int i = 0; i < 16; i++) wb[i] = wp[(size_t)(base + i) * OUT];
#pragma unroll
        for (int i = 0; i < 16; i++) acc = fmaf(pp[base + i], wb[i], acc);
    }
    red[seg][tid & 31] = acc;
    __syncthreads();

    if (tid < 32) {
        float a = bv[ot * 32 + tid];
#pragma unroll
        for (int k = 0; k < 16; k++) a += red[k][tid];
        out[(size_t)b * OUT + ot * 32 + tid] = tanhf(a);
    }
}

extern "C" void kernel_launch(void* const* d_in, const int* in_sizes, int n_in,
                              void* d_out, int out_size) {
    const float* hs = (const float*)d_in[0];
    const float* W1 = (const float*)d_in[1];
    const float* b1 = (const float*)d_in[2];
    const float* Wv = (const float*)d_in[3];
    const float* bv = (const float*)d_in[4];
    float* out = (float*)d_out;

    ht_kernel<<<dim3(32, HC), 256>>>(hs, W1, b1);
    v_kernel<<<dim3(128, 8), 256>>>(W1);
    main_pass_kernel<<<dim3(NP, B), 256>>>(hs);
    tail_kernel<<<dim3(B, 8), 512>>>(Wv, bv, out);
}